// round 1
// baseline (speedup 1.0000x reference)
#include <cuda_runtime.h>
#include <cuda_fp16.h>
#include <cstdint>

// ---------------- problem constants ----------------
#define D_MODEL 2048
#define NHEADS  16
#define DHEAD   128
#define SEQ     2048
#define BATCH   2
#define MROWS   (BATCH*SEQ)      // 4096
#define NQKV    (3*D_MODEL)      // 6144

// ---------------- device scratch (no allocations allowed) ----------------
__device__ __half g_wq[(size_t)NQKV*D_MODEL];        // ternary qkv weights (exact in fp16)
__device__ __half g_wo[(size_t)D_MODEL*D_MODEL];     // ternary out weights
__device__ __half g_xh[(size_t)MROWS*D_MODEL];       // x in fp16
__device__ __half g_qkv[(size_t)3*BATCH*NHEADS*SEQ*DHEAD]; // [t][b][h][s][d]
__device__ __half g_ao[(size_t)MROWS*D_MODEL];       // attention output [b,s,h*128+d]
__device__ float  g_part[2][2048];
__device__ float  g_scales[2];                        // [0]=qkv scale, [1]=out scale

// ---------------- small helpers ----------------
__device__ __forceinline__ unsigned smem_u32(const void* p) {
    return (unsigned)__cvta_generic_to_shared(p);
}
__device__ __forceinline__ void ldm_x4(unsigned* r, unsigned addr) {
    asm volatile("ldmatrix.sync.aligned.m8n8.x4.shared.b16 {%0,%1,%2,%3}, [%4];"
                 : "=r"(r[0]), "=r"(r[1]), "=r"(r[2]), "=r"(r[3]) : "r"(addr));
}
__device__ __forceinline__ void ldm_x4_t(unsigned* r, unsigned addr) {
    asm volatile("ldmatrix.sync.aligned.m8n8.x4.trans.shared.b16 {%0,%1,%2,%3}, [%4];"
                 : "=r"(r[0]), "=r"(r[1]), "=r"(r[2]), "=r"(r[3]) : "r"(addr));
}
__device__ __forceinline__ void mma16816(float* c, const unsigned* a, const unsigned* b) {
    asm volatile(
        "mma.sync.aligned.m16n8k16.row.col.f32.f16.f16.f32 "
        "{%0,%1,%2,%3}, {%4,%5,%6,%7}, {%8,%9}, {%0,%1,%2,%3};"
        : "+f"(c[0]), "+f"(c[1]), "+f"(c[2]), "+f"(c[3])
        : "r"(a[0]), "r"(a[1]), "r"(a[2]), "r"(a[3]), "r"(b[0]), "r"(b[1]));
}
__device__ __forceinline__ unsigned pack2(float a, float b) {
    __half2 h = __floats2half2_rn(a, b);
    return *reinterpret_cast<unsigned*>(&h);
}
__device__ __forceinline__ void cp16(void* dst, const void* src) {
    unsigned s = smem_u32(dst);
    asm volatile("cp.async.cg.shared.global [%0], [%1], 16;" :: "r"(s), "l"(src));
}

// ---------------- scale reduction ----------------
__global__ void reduce_abs_kernel(const float* __restrict__ w, int n, int slot) {
    float s = 0.f;
    for (int i = blockIdx.x * blockDim.x + threadIdx.x; i < n; i += gridDim.x * blockDim.x)
        s += fabsf(w[i]);
    __shared__ float sh[256];
    sh[threadIdx.x] = s; __syncthreads();
    for (int o = 128; o > 0; o >>= 1) {
        if (threadIdx.x < o) sh[threadIdx.x] += sh[threadIdx.x + o];
        __syncthreads();
    }
    if (threadIdx.x == 0) g_part[slot][blockIdx.x] = sh[0];
}

__global__ void finalize_scales_kernel() {
    __shared__ double sh[256];
    int t = threadIdx.x;
    for (int slot = 0; slot < 2; slot++) {
        double s = 0.0;
        for (int i = t; i < 2048; i += 256) s += (double)g_part[slot][i];
        sh[t] = s; __syncthreads();
        for (int o = 128; o > 0; o >>= 1) {
            if (t < o) sh[t] += sh[t + o];
            __syncthreads();
        }
        if (t == 0) {
            double n = (slot == 0) ? (double)NQKV * D_MODEL : (double)D_MODEL * D_MODEL;
            g_scales[slot] = fmaxf((float)(sh[0] / n), 1e-5f);
        }
        __syncthreads();
    }
}

// ---------------- quantize weights to ternary fp16 ----------------
__global__ void quantize_kernel(const float4* __restrict__ w, int n4, int slot) {
    int i = blockIdx.x * blockDim.x + threadIdx.x;
    if (i >= n4) return;
    __half* out = (slot == 0) ? g_wq : g_wo;
    float sc = g_scales[slot];
    float4 v = w[i];
    __half h[4];
    h[0] = __float2half_rn(fminf(fmaxf(rintf(v.x / sc), -1.f), 1.f));
    h[1] = __float2half_rn(fminf(fmaxf(rintf(v.y / sc), -1.f), 1.f));
    h[2] = __float2half_rn(fminf(fmaxf(rintf(v.z / sc), -1.f), 1.f));
    h[3] = __float2half_rn(fminf(fmaxf(rintf(v.w / sc), -1.f), 1.f));
    *reinterpret_cast<uint2*>(out + (size_t)4 * i) = *reinterpret_cast<uint2*>(h);
}

__global__ void convert_x_kernel(const float4* __restrict__ x, int n4) {
    int i = blockIdx.x * blockDim.x + threadIdx.x;
    if (i >= n4) return;
    float4 v = x[i];
    __half h[4];
    h[0] = __float2half_rn(v.x); h[1] = __float2half_rn(v.y);
    h[2] = __float2half_rn(v.z); h[3] = __float2half_rn(v.w);
    *reinterpret_cast<uint2*>(g_xh + (size_t)4 * i) = *reinterpret_cast<uint2*>(h);
}

// ---------------- GEMM: C[M,N] = A[M,K] * B[N,K]^T * scale ----------------
// MODE 0: A=g_xh (4096x2048), B=g_wq (6144x2048) -> g_qkv [t][b][h][s][d] fp16
// MODE 1: A=g_ao (4096x2048), B=g_wo (2048x2048) -> outF row-major fp32
template<int MODE>
__global__ void __launch_bounds__(256) gemm_kernel(float* __restrict__ outF) {
    constexpr int N = (MODE == 0) ? NQKV : D_MODEL;
    constexpr int K = D_MODEL;
    const __half* __restrict__ A  = (MODE == 0) ? g_xh : g_ao;
    const __half* __restrict__ Bw = (MODE == 0) ? g_wq : g_wo;

    __shared__ __half sA[2][128][40];
    __shared__ __half sB[2][128][40];

    const int tid = threadIdx.x;
    const int lane = tid & 31, warp = tid >> 5;
    const int wm = warp & 3, wn = warp >> 2;      // 4 x 2 warp grid
    const int bm = blockIdx.y * 128, bn = blockIdx.x * 128;

    float acc[2][8][4];
#pragma unroll
    for (int i = 0; i < 2; i++)
#pragma unroll
        for (int j = 0; j < 8; j++)
#pragma unroll
            for (int e = 0; e < 4; e++) acc[i][j][e] = 0.f;

    auto load_stage = [&](int s, int kt) {
        int k0 = kt * 32;
#pragma unroll
        for (int i = 0; i < 2; i++) {
            int id = tid + 256 * i;
            int row = id >> 2, c = (id & 3) * 8;
            cp16(&sA[s][row][c], A  + (size_t)(bm + row) * K + k0 + c);
            cp16(&sB[s][row][c], Bw + (size_t)(bn + row) * K + k0 + c);
        }
        asm volatile("cp.async.commit_group;");
    };

    load_stage(0, 0);
    const int KT = K / 32;
    for (int kt = 0; kt < KT; kt++) {
        if (kt + 1 < KT) {
            load_stage((kt + 1) & 1, kt + 1);
            asm volatile("cp.async.wait_group 1;");
        } else {
            asm volatile("cp.async.wait_group 0;");
        }
        __syncthreads();
        int s = kt & 1;
#pragma unroll
        for (int ks = 0; ks < 2; ks++) {
            unsigned aF[2][4], bF[8][2];
#pragma unroll
            for (int mt = 0; mt < 2; mt++)
                ldm_x4(aF[mt], smem_u32(&sA[s][wm * 32 + mt * 16 + (lane & 15)][ks * 16 + (lane >> 4) * 8]));
#pragma unroll
            for (int p = 0; p < 4; p++) {
                unsigned r[4];
                ldm_x4(r, smem_u32(&sB[s][wn * 64 + p * 16 + (lane & 15)][ks * 16 + (lane >> 4) * 8]));
                bF[2 * p][0] = r[0]; bF[2 * p][1] = r[2];
                bF[2 * p + 1][0] = r[1]; bF[2 * p + 1][1] = r[3];
            }
#pragma unroll
            for (int mt = 0; mt < 2; mt++)
#pragma unroll
                for (int nt = 0; nt < 8; nt++)
                    mma16816(acc[mt][nt], aF[mt], bF[nt]);
        }
        __syncthreads();
    }

    float scale = g_scales[MODE];
#pragma unroll
    for (int mt = 0; mt < 2; mt++) {
        int m0 = bm + wm * 32 + mt * 16 + (lane >> 2);
#pragma unroll
        for (int nt = 0; nt < 8; nt++) {
            int n0 = bn + wn * 64 + nt * 8 + (lane & 3) * 2;
            if (MODE == 0) {
#pragma unroll
                for (int rr = 0; rr < 2; rr++) {
                    int m = m0 + rr * 8;
                    int t_ = n0 >> 11, rem = n0 & 2047;
                    int h = rem >> 7, d = rem & 127;
                    int b = m >> 11, sidx = m & 2047;
                    size_t idx = (((size_t)(t_ * BATCH + b) * NHEADS + h) * SEQ + sidx) * DHEAD + d;
                    *reinterpret_cast<__half2*>(&g_qkv[idx]) =
                        __floats2half2_rn(acc[mt][nt][2 * rr] * scale, acc[mt][nt][2 * rr + 1] * scale);
                }
            } else {
                float2 v0 = {acc[mt][nt][0] * scale, acc[mt][nt][1] * scale};
                float2 v1 = {acc[mt][nt][2] * scale, acc[mt][nt][3] * scale};
                *reinterpret_cast<float2*>(&outF[(size_t)m0 * N + n0]) = v0;
                *reinterpret_cast<float2*>(&outF[(size_t)(m0 + 8) * N + n0]) = v1;
            }
        }
    }
}

// ---------------- RoPE (half-split / NeoX), in place on q and k ----------------
__global__ void rope_kernel() {
    int idx = blockIdx.x * blockDim.x + threadIdx.x;   // [b][h][s][d<64], 2^22 total
    if (idx >= BATCH * NHEADS * SEQ * 64) return;
    int d = idx & 63;
    int s = (idx >> 6) & 2047;
    int h = (idx >> 17) & 15;
    int b = idx >> 21;
    float freq = powf(10000.0f, -(float)d / 64.0f);
    float ang = (float)s * freq;
    float sn, cs;
    sincosf(ang, &sn, &cs);
#pragma unroll
    for (int tt = 0; tt < 2; tt++) {   // 0=q, 1=k
        size_t base = (((size_t)(tt * BATCH + b) * NHEADS + h) * SEQ + s) * DHEAD;
        float x1 = __half2float(g_qkv[base + d]);
        float x2 = __half2float(g_qkv[base + d + 64]);
        g_qkv[base + d]      = __float2half_rn(x1 * cs - x2 * sn);
        g_qkv[base + d + 64] = __float2half_rn(x1 * sn + x2 * cs);
    }
}

// ---------------- causal flash attention, Br=Bc=64, 4 warps ----------------
__global__ void __launch_bounds__(128) flash_kernel() {
    const int qt = (gridDim.x - 1) - blockIdx.x;   // heavy tiles scheduled first
    const int bh = blockIdx.y;
    const int b = bh >> 4, h = bh & 15;
    const int lane = threadIdx.x & 31, warp = threadIdx.x >> 5;

    const __half* __restrict__ Qp = g_qkv + ((size_t)(b * NHEADS + h)) * SEQ * DHEAD;
    const __half* __restrict__ Kp = g_qkv + ((size_t)((BATCH + b) * NHEADS + h)) * SEQ * DHEAD;
    const __half* __restrict__ Vp = g_qkv + ((size_t)((2 * BATCH + b) * NHEADS + h)) * SEQ * DHEAD;

    __shared__ __half sK[64][136];
    __shared__ __half sV[64][136];

    // stage Q through sK, cache Q fragments in registers
#pragma unroll
    for (int i = 0; i < 8; i++) {
        int c = threadIdx.x + i * 128;
        int row = c >> 4, off = (c & 15) * 8;
        *reinterpret_cast<uint4*>(&sK[row][off]) =
            *reinterpret_cast<const uint4*>(Qp + (size_t)(qt * 64 + row) * DHEAD + off);
    }
    __syncthreads();
    unsigned qF[8][4];
#pragma unroll
    for (int ks = 0; ks < 8; ks++)
        ldm_x4(qF[ks], smem_u32(&sK[warp * 16 + (lane & 15)][ks * 16 + (lane >> 4) * 8]));
    __syncthreads();

    float oacc[16][4];
#pragma unroll
    for (int i = 0; i < 16; i++)
#pragma unroll
        for (int e = 0; e < 4; e++) oacc[i][e] = 0.f;
    float mx0 = -1e30f, mx1 = -1e30f, l0 = 0.f, l1 = 0.f;
    const float sscale = 0.08838834764831845f;  // 1/sqrt(128)
    const int qrow0 = qt * 64 + warp * 16 + (lane >> 2);

    for (int j = 0; j <= qt; j++) {
#pragma unroll
        for (int i = 0; i < 8; i++) {
            int c = threadIdx.x + i * 128;
            int row = c >> 4, off = (c & 15) * 8;
            *reinterpret_cast<uint4*>(&sK[row][off]) =
                *reinterpret_cast<const uint4*>(Kp + (size_t)(j * 64 + row) * DHEAD + off);
            *reinterpret_cast<uint4*>(&sV[row][off]) =
                *reinterpret_cast<const uint4*>(Vp + (size_t)(j * 64 + row) * DHEAD + off);
        }
        __syncthreads();

        // S = Q K^T
        float sacc[8][4];
#pragma unroll
        for (int nt = 0; nt < 8; nt++)
#pragma unroll
            for (int e = 0; e < 4; e++) sacc[nt][e] = 0.f;
#pragma unroll
        for (int ks = 0; ks < 8; ks++) {
            unsigned bF[8][2];
#pragma unroll
            for (int p = 0; p < 4; p++) {
                unsigned r[4];
                ldm_x4(r, smem_u32(&sK[p * 16 + (lane & 15)][ks * 16 + (lane >> 4) * 8]));
                bF[2 * p][0] = r[0]; bF[2 * p][1] = r[2];
                bF[2 * p + 1][0] = r[1]; bF[2 * p + 1][1] = r[3];
            }
#pragma unroll
            for (int nt = 0; nt < 8; nt++) mma16816(sacc[nt], qF[ks], bF[nt]);
        }

        // scale + causal mask (only on diagonal block)
#pragma unroll
        for (int nt = 0; nt < 8; nt++) {
            int col = j * 64 + nt * 8 + (lane & 3) * 2;
#pragma unroll
            for (int e = 0; e < 4; e++) {
                int cc = col + (e & 1);
                int qr = qrow0 + (e >> 1) * 8;
                float v = sacc[nt][e] * sscale;
                if (j == qt && cc > qr) v = -1e30f;
                sacc[nt][e] = v;
            }
        }

        // online softmax
        float rm0 = -1e30f, rm1 = -1e30f;
#pragma unroll
        for (int nt = 0; nt < 8; nt++) {
            rm0 = fmaxf(rm0, fmaxf(sacc[nt][0], sacc[nt][1]));
            rm1 = fmaxf(rm1, fmaxf(sacc[nt][2], sacc[nt][3]));
        }
        rm0 = fmaxf(rm0, __shfl_xor_sync(0xffffffffu, rm0, 1));
        rm0 = fmaxf(rm0, __shfl_xor_sync(0xffffffffu, rm0, 2));
        rm1 = fmaxf(rm1, __shfl_xor_sync(0xffffffffu, rm1, 1));
        rm1 = fmaxf(rm1, __shfl_xor_sync(0xffffffffu, rm1, 2));
        float mn0 = fmaxf(mx0, rm0), mn1 = fmaxf(mx1, rm1);
        float al0 = __expf(mx0 - mn0), al1 = __expf(mx1 - mn1);
        mx0 = mn0; mx1 = mn1;

        float rs0 = 0.f, rs1 = 0.f;
#pragma unroll
        for (int nt = 0; nt < 8; nt++) {
            float p0 = __expf(sacc[nt][0] - mn0), p1 = __expf(sacc[nt][1] - mn0);
            float p2 = __expf(sacc[nt][2] - mn1), p3 = __expf(sacc[nt][3] - mn1);
            sacc[nt][0] = p0; sacc[nt][1] = p1; sacc[nt][2] = p2; sacc[nt][3] = p3;
            rs0 += p0 + p1; rs1 += p2 + p3;
        }
        rs0 += __shfl_xor_sync(0xffffffffu, rs0, 1);
        rs0 += __shfl_xor_sync(0xffffffffu, rs0, 2);
        rs1 += __shfl_xor_sync(0xffffffffu, rs1, 1);
        rs1 += __shfl_xor_sync(0xffffffffu, rs1, 2);
        l0 = l0 * al0 + rs0; l1 = l1 * al1 + rs1;
#pragma unroll
        for (int i = 0; i < 16; i++) {
            oacc[i][0] *= al0; oacc[i][1] *= al0;
            oacc[i][2] *= al1; oacc[i][3] *= al1;
        }

        // P fragments (fp16)
        unsigned aP[4][4];
#pragma unroll
        for (int kk = 0; kk < 4; kk++) {
            aP[kk][0] = pack2(sacc[2 * kk][0], sacc[2 * kk][1]);
            aP[kk][1] = pack2(sacc[2 * kk][2], sacc[2 * kk][3]);
            aP[kk][2] = pack2(sacc[2 * kk + 1][0], sacc[2 * kk + 1][1]);
            aP[kk][3] = pack2(sacc[2 * kk + 1][2], sacc[2 * kk + 1][3]);
        }

        // O += P V   (V loaded via ldmatrix.trans)
#pragma unroll
        for (int kk = 0; kk < 4; kk++) {
            int kvrow = kk * 16 + ((lane >> 3) & 1) * 8 + (lane & 7);
#pragma unroll
            for (int p = 0; p < 8; p++) {
                unsigned r[4];
                int dcol = p * 16 + (lane >> 4) * 8;
                ldm_x4_t(r, smem_u32(&sV[kvrow][dcol]));
                unsigned b0[2] = {r[0], r[1]}, b1[2] = {r[2], r[3]};
                mma16816(oacc[2 * p], aP[kk], b0);
                mma16816(oacc[2 * p + 1], aP[kk], b1);
            }
        }
        __syncthreads();
    }

    float il0 = 1.f / l0, il1 = 1.f / l1;
    int s0 = qt * 64 + warp * 16 + (lane >> 2);
    size_t rb0 = ((size_t)(b * SEQ + s0)) * D_MODEL + h * DHEAD;
    size_t rb1 = rb0 + (size_t)8 * D_MODEL;
#pragma unroll
    for (int p = 0; p < 16; p++) {
        int d = p * 8 + (lane & 3) * 2;
        *reinterpret_cast<__half2*>(&g_ao[rb0 + d]) = __floats2half2_rn(oacc[p][0] * il0, oacc[p][1] * il0);
        *reinterpret_cast<__half2*>(&g_ao[rb1 + d]) = __floats2half2_rn(oacc[p][2] * il1, oacc[p][3] * il1);
    }
}

// ---------------- launcher ----------------
extern "C" void kernel_launch(void* const* d_in, const int* in_sizes, int n_in,
                              void* d_out, int out_size) {
    const float* x    = (const float*)d_in[0];   // [B,S,D] fp32
    const float* wqkv = (const float*)d_in[1];   // [6144,2048] fp32
    const float* wout = (const float*)d_in[2];   // [2048,2048] fp32
    // d_in[3] = mask (causal, known statically; unused)

    reduce_abs_kernel<<<2048, 256>>>(wqkv, NQKV * D_MODEL, 0);
    reduce_abs_kernel<<<2048, 256>>>(wout, D_MODEL * D_MODEL, 1);
    finalize_scales_kernel<<<1, 256>>>();

    quantize_kernel<<<(NQKV * D_MODEL / 4) / 256, 256>>>((const float4*)wqkv, NQKV * D_MODEL / 4, 0);
    quantize_kernel<<<(D_MODEL * D_MODEL / 4) / 256, 256>>>((const float4*)wout, D_MODEL * D_MODEL / 4, 1);
    convert_x_kernel<<<(MROWS * D_MODEL / 4) / 256, 256>>>((const float4*)x, MROWS * D_MODEL / 4);

    gemm_kernel<0><<<dim3(NQKV / 128, MROWS / 128), 256>>>(nullptr);
    rope_kernel<<<(BATCH * NHEADS * SEQ * 64) / 256, 256>>>();
    flash_kernel<<<dim3(SEQ / 64, BATCH * NHEADS), 128>>>();
    gemm_kernel<1><<<dim3(D_MODEL / 128, MROWS / 128), 256>>>((float*)d_out);
}

// round 4
// speedup vs baseline: 1.2092x; 1.2092x over previous
#include <cuda_runtime.h>
#include <cuda_fp16.h>
#include <cstdint>

// ---------------- problem constants ----------------
#define D_MODEL 2048
#define NHEADS  16
#define DHEAD   128
#define SEQ     2048
#define BATCH   2
#define MROWS   (BATCH*SEQ)      // 4096
#define NQKV    (3*D_MODEL)      // 6144

// ---------------- device scratch ----------------
__device__ __half g_wq[(size_t)NQKV*D_MODEL];
__device__ __half g_wo[(size_t)D_MODEL*D_MODEL];
__device__ __half g_xh[(size_t)MROWS*D_MODEL];
__device__ __half g_qkv[(size_t)3*BATCH*NHEADS*SEQ*DHEAD]; // [t][b][h][s][d]
__device__ __half g_ao[(size_t)MROWS*D_MODEL];
__device__ float  g_part[2][2048];
__device__ float  g_scales[2];

// ---------------- helpers ----------------
__device__ __forceinline__ unsigned smem_u32(const void* p) {
    return (unsigned)__cvta_generic_to_shared(p);
}
__device__ __forceinline__ void ldm_x4(unsigned* r, unsigned addr) {
    asm volatile("ldmatrix.sync.aligned.m8n8.x4.shared.b16 {%0,%1,%2,%3}, [%4];"
                 : "=r"(r[0]), "=r"(r[1]), "=r"(r[2]), "=r"(r[3]) : "r"(addr));
}
__device__ __forceinline__ void ldm_x4_t(unsigned* r, unsigned addr) {
    asm volatile("ldmatrix.sync.aligned.m8n8.x4.trans.shared.b16 {%0,%1,%2,%3}, [%4];"
                 : "=r"(r[0]), "=r"(r[1]), "=r"(r[2]), "=r"(r[3]) : "r"(addr));
}
__device__ __forceinline__ void mma16816(float* c, const unsigned* a, const unsigned* b) {
    asm volatile(
        "mma.sync.aligned.m16n8k16.row.col.f32.f16.f16.f32 "
        "{%0,%1,%2,%3}, {%4,%5,%6,%7}, {%8,%9}, {%0,%1,%2,%3};"
        : "+f"(c[0]), "+f"(c[1]), "+f"(c[2]), "+f"(c[3])
        : "r"(a[0]), "r"(a[1]), "r"(a[2]), "r"(a[3]), "r"(b[0]), "r"(b[1]));
}
__device__ __forceinline__ unsigned pack2(float a, float b) {
    __half2 h = __floats2half2_rn(a, b);
    return *reinterpret_cast<unsigned*>(&h);
}
__device__ __forceinline__ void cp16(uint32_t saddr, const void* gaddr) {
    asm volatile("cp.async.cg.shared.global [%0], [%1], 16;" :: "r"(saddr), "l"(gaddr));
}
#define CP_COMMIT() asm volatile("cp.async.commit_group;" ::: "memory")
#define CP_WAIT1()  asm volatile("cp.async.wait_group 1;" ::: "memory")

// ---------------- scale reduction / quantize / convert ----------------
__global__ void reduce_abs_kernel(const float* __restrict__ w, int n, int slot) {
    float s = 0.f;
    for (int i = blockIdx.x * blockDim.x + threadIdx.x; i < n; i += gridDim.x * blockDim.x)
        s += fabsf(w[i]);
    __shared__ float sh[256];
    sh[threadIdx.x] = s; __syncthreads();
    for (int o = 128; o > 0; o >>= 1) {
        if (threadIdx.x < o) sh[threadIdx.x] += sh[threadIdx.x + o];
        __syncthreads();
    }
    if (threadIdx.x == 0) g_part[slot][blockIdx.x] = sh[0];
}

__global__ void finalize_scales_kernel() {
    __shared__ double sh[256];
    int t = threadIdx.x;
    for (int slot = 0; slot < 2; slot++) {
        double s = 0.0;
        for (int i = t; i < 2048; i += 256) s += (double)g_part[slot][i];
        sh[t] = s; __syncthreads();
        for (int o = 128; o > 0; o >>= 1) {
            if (t < o) sh[t] += sh[t + o];
            __syncthreads();
        }
        if (t == 0) {
            double n = (slot == 0) ? (double)NQKV * D_MODEL : (double)D_MODEL * D_MODEL;
            g_scales[slot] = fmaxf((float)(sh[0] / n), 1e-5f);
        }
        __syncthreads();
    }
}

__global__ void quantize_kernel(const float4* __restrict__ w, int n4, int slot) {
    int i = blockIdx.x * blockDim.x + threadIdx.x;
    if (i >= n4) return;
    __half* out = (slot == 0) ? g_wq : g_wo;
    float sc = g_scales[slot];
    float4 v = w[i];
    __half h[4];
    h[0] = __float2half_rn(fminf(fmaxf(rintf(v.x / sc), -1.f), 1.f));
    h[1] = __float2half_rn(fminf(fmaxf(rintf(v.y / sc), -1.f), 1.f));
    h[2] = __float2half_rn(fminf(fmaxf(rintf(v.z / sc), -1.f), 1.f));
    h[3] = __float2half_rn(fminf(fmaxf(rintf(v.w / sc), -1.f), 1.f));
    *reinterpret_cast<uint2*>(out + (size_t)4 * i) = *reinterpret_cast<uint2*>(h);
}

__global__ void convert_x_kernel(const float4* __restrict__ x, int n4) {
    int i = blockIdx.x * blockDim.x + threadIdx.x;
    if (i >= n4) return;
    float4 v = x[i];
    __half h[4];
    h[0] = __float2half_rn(v.x); h[1] = __float2half_rn(v.y);
    h[2] = __float2half_rn(v.z); h[3] = __float2half_rn(v.w);
    *reinterpret_cast<uint2*>(g_xh + (size_t)4 * i) = *reinterpret_cast<uint2*>(h);
}

// ---------------- GEMM: C[M,N] = A[M,K]*B[N,K]^T*scale (mma.sync, BK=64, 3-stage) ----------------
// MODE 0: A=g_xh, B=g_wq -> g_qkv [t][b][h][s][d] fp16
// MODE 1: A=g_ao, B=g_wo -> outF fp32 row-major
template<int MODE>
__global__ void __launch_bounds__(256, 2) gemm_hmma(float* __restrict__ outF) {
    constexpr int K  = D_MODEL;
    constexpr int KT = K / 64;                 // 32 K-steps
    constexpr int ROWB = 144;                  // 72 halfs padded row (bytes)
    constexpr int STG = 128 * ROWB;            // 18432 bytes/stage/matrix

    extern __shared__ __align__(128) uint8_t smem[];
    const uint32_t sbase = smem_u32(smem);
    const uint32_t offA = 0, offB = 3 * STG;

    const __half* __restrict__ Aop = (MODE == 0) ? g_xh : g_ao;
    const __half* __restrict__ Bop = (MODE == 0) ? g_wq : g_wo;
    const int tid = threadIdx.x, warp = tid >> 5, lane = tid & 31;
    const int wm = warp & 3, wn = warp >> 2;   // 4x2 warp grid, warp tile 32x64
    const int bm = blockIdx.y * 128, bn = blockIdx.x * 128;

    const __half* gA = Aop + (size_t)bm * K;
    const __half* gB = Bop + (size_t)bn * K;

    // per-thread load coords: rows of 64 halfs (128B) -> 8 chunks/row
    const int lrow = tid >> 3;                 // base row (adds i*32)
    const int lch  = (tid & 7) * 8;            // half offset within 64-half row

    auto load_stage = [&](int kt) {
        const int slot = kt % 3;
        const __half* ga = gA + kt * 64;
        const __half* gb = gB + kt * 64;
        const uint32_t sa = sbase + offA + slot * STG;
        const uint32_t sb = sbase + offB + slot * STG;
#pragma unroll
        for (int i = 0; i < 4; i++) {
            int row = lrow + i * 32;
            uint32_t so = (uint32_t)(row * ROWB + lch * 2);
            size_t go = (size_t)row * K + lch;
            cp16(sa + so, ga + go);
            cp16(sb + so, gb + go);
        }
    };

    float acc[2][8][4];
#pragma unroll
    for (int i = 0; i < 2; i++)
#pragma unroll
        for (int j = 0; j < 8; j++)
#pragma unroll
            for (int e = 0; e < 4; e++) acc[i][j][e] = 0.f;

    load_stage(0); CP_COMMIT();
    load_stage(1); CP_COMMIT();

    for (int kt = 0; kt < KT; kt++) {
        CP_WAIT1();                 // group kt complete
        __syncthreads();
        if (kt + 2 < KT) load_stage(kt + 2);
        CP_COMMIT();                // always commit (empty group ok)

        const int slot = kt % 3;
        const uint32_t aB = sbase + offA + slot * STG;
        const uint32_t bB = sbase + offB + slot * STG;
#pragma unroll
        for (int ks = 0; ks < 4; ks++) {
            const uint32_t kcol = (ks * 16 + (lane >> 4) * 8) * 2;
            unsigned aF[2][4], bF[8][2];
#pragma unroll
            for (int mt = 0; mt < 2; mt++)
                ldm_x4(aF[mt], aB + (wm * 32 + mt * 16 + (lane & 15)) * ROWB + kcol);
#pragma unroll
            for (int p = 0; p < 4; p++) {
                unsigned r[4];
                ldm_x4(r, bB + (wn * 64 + p * 16 + (lane & 15)) * ROWB + kcol);
                bF[2 * p][0] = r[0]; bF[2 * p][1] = r[2];
                bF[2 * p + 1][0] = r[1]; bF[2 * p + 1][1] = r[3];
            }
#pragma unroll
            for (int mt = 0; mt < 2; mt++)
#pragma unroll
                for (int nt = 0; nt < 8; nt++)
                    mma16816(acc[mt][nt], aF[mt], bF[nt]);
        }
    }

    const float scale = g_scales[MODE];
#pragma unroll
    for (int mt = 0; mt < 2; mt++) {
        int m0 = bm + wm * 32 + mt * 16 + (lane >> 2);
#pragma unroll
        for (int nt = 0; nt < 8; nt++) {
            int n0 = bn + wn * 64 + nt * 8 + (lane & 3) * 2;
            if (MODE == 0) {
#pragma unroll
                for (int rr = 0; rr < 2; rr++) {
                    int m = m0 + rr * 8;
                    int t_ = n0 >> 11, rem = n0 & 2047;
                    int h = rem >> 7, d = rem & 127;
                    int b = m >> 11, sidx = m & 2047;
                    size_t idx = (((size_t)(t_ * BATCH + b) * NHEADS + h) * SEQ + sidx) * DHEAD + d;
                    *reinterpret_cast<__half2*>(&g_qkv[idx]) =
                        __floats2half2_rn(acc[mt][nt][2 * rr] * scale, acc[mt][nt][2 * rr + 1] * scale);
                }
            } else {
                float2 v0 = {acc[mt][nt][0] * scale, acc[mt][nt][1] * scale};
                float2 v1 = {acc[mt][nt][2] * scale, acc[mt][nt][3] * scale};
                *reinterpret_cast<float2*>(&outF[(size_t)m0 * D_MODEL + n0]) = v0;
                *reinterpret_cast<float2*>(&outF[(size_t)(m0 + 8) * D_MODEL + n0]) = v1;
            }
        }
    }
}

// ---------------- RoPE (half-split), in place on q and k ----------------
__global__ void rope_kernel() {
    int idx = blockIdx.x * blockDim.x + threadIdx.x;
    if (idx >= BATCH * NHEADS * SEQ * 64) return;
    int d = idx & 63;
    int s = (idx >> 6) & 2047;
    int h = (idx >> 17) & 15;
    int b = idx >> 21;
    float freq = powf(10000.0f, -(float)d / 64.0f);
    float ang = (float)s * freq;
    float sn, cs;
    sincosf(ang, &sn, &cs);
#pragma unroll
    for (int tt = 0; tt < 2; tt++) {
        size_t base = (((size_t)(tt * BATCH + b) * NHEADS + h) * SEQ + s) * DHEAD;
        float x1 = __half2float(g_qkv[base + d]);
        float x2 = __half2float(g_qkv[base + d + 64]);
        g_qkv[base + d]      = __float2half_rn(x1 * cs - x2 * sn);
        g_qkv[base + d + 64] = __float2half_rn(x1 * sn + x2 * cs);
    }
}

// ---------------- causal flash attention, Br=Bc=64, 3-stage cp.async ----------------
__global__ void __launch_bounds__(128) flash_kernel() {
    constexpr int ROWB = 272;                 // 136 halfs padded row (bytes)
    constexpr int KSTG = 64 * ROWB;           // 17408 bytes/stage/matrix
    extern __shared__ __align__(128) uint8_t smem[];
    const uint32_t sbase = smem_u32(smem);
    const uint32_t offK = 0, offV = 3 * KSTG;

    const int qt = (gridDim.x - 1) - blockIdx.x;
    const int bh = blockIdx.y;
    const int b = bh >> 4, h = bh & 15;
    const int tid = threadIdx.x, lane = tid & 31, warp = tid >> 5;

    const __half* __restrict__ Qp = g_qkv + ((size_t)(b * NHEADS + h)) * SEQ * DHEAD;
    const __half* __restrict__ Kp = g_qkv + ((size_t)((BATCH + b) * NHEADS + h)) * SEQ * DHEAD;
    const __half* __restrict__ Vp = g_qkv + ((size_t)((2 * BATCH + b) * NHEADS + h)) * SEQ * DHEAD;

    // stage Q via the stage-0 K region, keep fragments in registers
    __half* sQ = reinterpret_cast<__half*>(smem);
#pragma unroll
    for (int i = 0; i < 8; i++) {
        int c = tid + i * 128;
        int row = c >> 4, off = (c & 15) * 8;
        *reinterpret_cast<uint4*>(&sQ[row * 136 + off]) =
            *reinterpret_cast<const uint4*>(Qp + (size_t)(qt * 64 + row) * DHEAD + off);
    }
    __syncthreads();
    unsigned qF[8][4];
#pragma unroll
    for (int ks = 0; ks < 8; ks++)
        ldm_x4(qF[ks], sbase + (warp * 16 + (lane & 15)) * ROWB + (ks * 16 + (lane >> 4) * 8) * 2);
    __syncthreads();

    // K/V rows are 128 halfs (256B) -> 16 chunks/row; 8 rows-iterations per thread
    const int lrow = tid >> 4;                // 0..7, +i*8
    const int lch  = (tid & 15) * 8;          // half offset 0..120
    auto load_kv = [&](int j) {
        const int slot = j % 3;
        const uint32_t sk = sbase + offK + slot * KSTG;
        const uint32_t sv = sbase + offV + slot * KSTG;
        const __half* gk = Kp + (size_t)j * 64 * DHEAD;
        const __half* gv = Vp + (size_t)j * 64 * DHEAD;
#pragma unroll
        for (int i = 0; i < 8; i++) {
            int row = lrow + i * 8;
            uint32_t so = (uint32_t)(row * ROWB + lch * 2);
            size_t go = (size_t)row * DHEAD + lch;
            cp16(sk + so, gk + go);
            cp16(sv + so, gv + go);
        }
    };

    load_kv(0); CP_COMMIT();
    if (1 <= qt) load_kv(1);
    CP_COMMIT();

    float oacc[16][4];
#pragma unroll
    for (int i = 0; i < 16; i++)
#pragma unroll
        for (int e = 0; e < 4; e++) oacc[i][e] = 0.f;
    float mx0 = -1e30f, mx1 = -1e30f, l0 = 0.f, l1 = 0.f;
    const float sscale = 0.08838834764831845f;
    const int qrow0 = qt * 64 + warp * 16 + (lane >> 2);

    for (int j = 0; j <= qt; j++) {
        CP_WAIT1();
        __syncthreads();
        if (j + 2 <= qt) load_kv(j + 2);
        CP_COMMIT();

        const int slot = j % 3;
        const uint32_t kB = sbase + offK + slot * KSTG;
        const uint32_t vB = sbase + offV + slot * KSTG;

        float sacc[8][4];
#pragma unroll
        for (int nt = 0; nt < 8; nt++)
#pragma unroll
            for (int e = 0; e < 4; e++) sacc[nt][e] = 0.f;
#pragma unroll
        for (int ks = 0; ks < 8; ks++) {
            const uint32_t kcol = (ks * 16 + (lane >> 4) * 8) * 2;
            unsigned bF[8][2];
#pragma unroll
            for (int p = 0; p < 4; p++) {
                unsigned r[4];
                ldm_x4(r, kB + (p * 16 + (lane & 15)) * ROWB + kcol);
                bF[2 * p][0] = r[0]; bF[2 * p][1] = r[2];
                bF[2 * p + 1][0] = r[1]; bF[2 * p + 1][1] = r[3];
            }
#pragma unroll
            for (int nt = 0; nt < 8; nt++) mma16816(sacc[nt], qF[ks], bF[nt]);
        }

#pragma unroll
        for (int nt = 0; nt < 8; nt++) {
            int col = j * 64 + nt * 8 + (lane & 3) * 2;
#pragma unroll
            for (int e = 0; e < 4; e++) {
                int cc = col + (e & 1);
                int qr = qrow0 + (e >> 1) * 8;
                float v = sacc[nt][e] * sscale;
                if (j == qt && cc > qr) v = -1e30f;
                sacc[nt][e] = v;
            }
        }

        float rm0 = -1e30f, rm1 = -1e30f;
#pragma unroll
        for (int nt = 0; nt < 8; nt++) {
            rm0 = fmaxf(rm0, fmaxf(sacc[nt][0], sacc[nt][1]));
            rm1 = fmaxf(rm1, fmaxf(sacc[nt][2], sacc[nt][3]));
        }
        rm0 = fmaxf(rm0, __shfl_xor_sync(0xffffffffu, rm0, 1));
        rm0 = fmaxf(rm0, __shfl_xor_sync(0xffffffffu, rm0, 2));
        rm1 = fmaxf(rm1, __shfl_xor_sync(0xffffffffu, rm1, 1));
        rm1 = fmaxf(rm1, __shfl_xor_sync(0xffffffffu, rm1, 2));
        float mn0 = fmaxf(mx0, rm0), mn1 = fmaxf(mx1, rm1);
        float al0 = __expf(mx0 - mn0), al1 = __expf(mx1 - mn1);
        mx0 = mn0; mx1 = mn1;

        float rs0 = 0.f, rs1 = 0.f;
#pragma unroll
        for (int nt = 0; nt < 8; nt++) {
            float p0 = __expf(sacc[nt][0] - mn0), p1 = __expf(sacc[nt][1] - mn0);
            float p2 = __expf(sacc[nt][2] - mn1), p3 = __expf(sacc[nt][3] - mn1);
            sacc[nt][0] = p0; sacc[nt][1] = p1; sacc[nt][2] = p2; sacc[nt][3] = p3;
            rs0 += p0 + p1; rs1 += p2 + p3;
        }
        rs0 += __shfl_xor_sync(0xffffffffu, rs0, 1);
        rs0 += __shfl_xor_sync(0xffffffffu, rs0, 2);
        rs1 += __shfl_xor_sync(0xffffffffu, rs1, 1);
        rs1 += __shfl_xor_sync(0xffffffffu, rs1, 2);
        l0 = l0 * al0 + rs0; l1 = l1 * al1 + rs1;
#pragma unroll
        for (int i = 0; i < 16; i++) {
            oacc[i][0] *= al0; oacc[i][1] *= al0;
            oacc[i][2] *= al1; oacc[i][3] *= al1;
        }

        unsigned aP[4][4];
#pragma unroll
        for (int kk = 0; kk < 4; kk++) {
            aP[kk][0] = pack2(sacc[2 * kk][0], sacc[2 * kk][1]);
            aP[kk][1] = pack2(sacc[2 * kk][2], sacc[2 * kk][3]);
            aP[kk][2] = pack2(sacc[2 * kk + 1][0], sacc[2 * kk + 1][1]);
            aP[kk][3] = pack2(sacc[2 * kk + 1][2], sacc[2 * kk + 1][3]);
        }

#pragma unroll
        for (int kk = 0; kk < 4; kk++) {
            int kvrow = kk * 16 + ((lane >> 3) & 1) * 8 + (lane & 7);
#pragma unroll
            for (int p = 0; p < 8; p++) {
                unsigned r[4];
                int dcol = p * 16 + (lane >> 4) * 8;
                ldm_x4_t(r, vB + kvrow * ROWB + dcol * 2);
                unsigned b0[2] = {r[0], r[1]}, b1[2] = {r[2], r[3]};
                mma16816(oacc[2 * p], aP[kk], b0);
                mma16816(oacc[2 * p + 1], aP[kk], b1);
            }
        }
    }

    float il0 = 1.f / l0, il1 = 1.f / l1;
    int s0 = qt * 64 + warp * 16 + (lane >> 2);
    size_t rb0 = ((size_t)(b * SEQ + s0)) * D_MODEL + h * DHEAD;
    size_t rb1 = rb0 + (size_t)8 * D_MODEL;
#pragma unroll
    for (int p = 0; p < 16; p++) {
        int d = p * 8 + (lane & 3) * 2;
        *reinterpret_cast<__half2*>(&g_ao[rb0 + d]) = __floats2half2_rn(oacc[p][0] * il0, oacc[p][1] * il0);
        *reinterpret_cast<__half2*>(&g_ao[rb1 + d]) = __floats2half2_rn(oacc[p][2] * il1, oacc[p][3] * il1);
    }
}

// ---------------- launcher ----------------
extern "C" void kernel_launch(void* const* d_in, const int* in_sizes, int n_in,
                              void* d_out, int out_size) {
    const float* x    = (const float*)d_in[0];
    const float* wqkv = (const float*)d_in[1];
    const float* wout = (const float*)d_in[2];
    // d_in[3] = causal mask (static; unused)

    constexpr int GEMM_SMEM  = 6 * 128 * 144;      // 110592
    constexpr int FLASH_SMEM = 6 * 64 * 272;       // 104448
    cudaFuncSetAttribute(gemm_hmma<0>, cudaFuncAttributeMaxDynamicSharedMemorySize, GEMM_SMEM);
    cudaFuncSetAttribute(gemm_hmma<1>, cudaFuncAttributeMaxDynamicSharedMemorySize, GEMM_SMEM);
    cudaFuncSetAttribute(flash_kernel, cudaFuncAttributeMaxDynamicSharedMemorySize, FLASH_SMEM);

    reduce_abs_kernel<<<2048, 256>>>(wqkv, NQKV * D_MODEL, 0);
    reduce_abs_kernel<<<2048, 256>>>(wout, D_MODEL * D_MODEL, 1);
    finalize_scales_kernel<<<1, 256>>>();

    quantize_kernel<<<(NQKV * D_MODEL / 4) / 256, 256>>>((const float4*)wqkv, NQKV * D_MODEL / 4, 0);
    quantize_kernel<<<(D_MODEL * D_MODEL / 4) / 256, 256>>>((const float4*)wout, D_MODEL * D_MODEL / 4, 1);
    convert_x_kernel<<<(MROWS * D_MODEL / 4) / 256, 256>>>((const float4*)x, MROWS * D_MODEL / 4);

    gemm_hmma<0><<<dim3(NQKV / 128, MROWS / 128), 256, GEMM_SMEM>>>(nullptr);
    rope_kernel<<<(BATCH * NHEADS * SEQ * 64) / 256, 256>>>();
    flash_kernel<<<dim3(SEQ / 64, BATCH * NHEADS), 128, FLASH_SMEM>>>();
    gemm_hmma<1><<<dim3(D_MODEL / 128, MROWS / 128), 256, GEMM_SMEM>>>((float*)d_out);
}

// round 6
// speedup vs baseline: 1.2533x; 1.0365x over previous
#include <cuda_runtime.h>
#include <cuda_fp16.h>
#include <cstdint>

// ---------------- problem constants ----------------
#define D_MODEL 2048
#define NHEADS  16
#define DHEAD   128
#define SEQ     2048
#define BATCH   2
#define MROWS   (BATCH*SEQ)      // 4096
#define NQKV    (3*D_MODEL)      // 6144

// ---------------- device scratch ----------------
__device__ __half g_wq[(size_t)NQKV*D_MODEL];
__device__ __half g_wo[(size_t)D_MODEL*D_MODEL];
__device__ __half g_xh[(size_t)MROWS*D_MODEL];
__device__ __half g_qkv[(size_t)3*BATCH*NHEADS*SEQ*DHEAD]; // [t][b][h][s][d]
__device__ __half g_ao[(size_t)MROWS*D_MODEL];
__device__ float  g_part[2][2048];
__device__ float  g_scales[2];

// ---------------- helpers ----------------
__device__ __forceinline__ unsigned smem_u32(const void* p) {
    return (unsigned)__cvta_generic_to_shared(p);
}
__device__ __forceinline__ void ldm_x4(unsigned* r, unsigned addr) {
    asm volatile("ldmatrix.sync.aligned.m8n8.x4.shared.b16 {%0,%1,%2,%3}, [%4];"
                 : "=r"(r[0]), "=r"(r[1]), "=r"(r[2]), "=r"(r[3]) : "r"(addr));
}
__device__ __forceinline__ void ldm_x4_t(unsigned* r, unsigned addr) {
    asm volatile("ldmatrix.sync.aligned.m8n8.x4.trans.shared.b16 {%0,%1,%2,%3}, [%4];"
                 : "=r"(r[0]), "=r"(r[1]), "=r"(r[2]), "=r"(r[3]) : "r"(addr));
}
__device__ __forceinline__ void mma16816(float* c, const unsigned* a, const unsigned* b) {
    asm volatile(
        "mma.sync.aligned.m16n8k16.row.col.f32.f16.f16.f32 "
        "{%0,%1,%2,%3}, {%4,%5,%6,%7}, {%8,%9}, {%0,%1,%2,%3};"
        : "+f"(c[0]), "+f"(c[1]), "+f"(c[2]), "+f"(c[3])
        : "r"(a[0]), "r"(a[1]), "r"(a[2]), "r"(a[3]), "r"(b[0]), "r"(b[1]));
}
__device__ __forceinline__ unsigned pack2(float a, float b) {
    __half2 h = __floats2half2_rn(a, b);
    return *reinterpret_cast<unsigned*>(&h);
}
__device__ __forceinline__ void cp16(uint32_t saddr, const void* gaddr) {
    asm volatile("cp.async.cg.shared.global [%0], [%1], 16;" :: "r"(saddr), "l"(gaddr));
}
#define CP_COMMIT() asm volatile("cp.async.commit_group;" ::: "memory")
#define CP_WAIT1()  asm volatile("cp.async.wait_group 1;" ::: "memory")

// ---------------- prep: fused abs-reduction over both weight tensors ----------------
__global__ void reduce_abs_all(const float* __restrict__ wq, const float* __restrict__ wo) {
    const int slot = (blockIdx.x < 2048) ? 0 : 1;
    const int bid  = (slot == 0) ? blockIdx.x : blockIdx.x - 2048;
    const int nblk = (slot == 0) ? 2048 : 1024;
    const float* w = (slot == 0) ? wq : wo;
    const int n = (slot == 0) ? NQKV * D_MODEL : D_MODEL * D_MODEL;
    float s = 0.f;
    for (int i = bid * blockDim.x + threadIdx.x; i < n; i += nblk * blockDim.x)
        s += fabsf(w[i]);
    __shared__ float sh[256];
    sh[threadIdx.x] = s; __syncthreads();
    for (int o = 128; o > 0; o >>= 1) {
        if (threadIdx.x < o) sh[threadIdx.x] += sh[threadIdx.x + o];
        __syncthreads();
    }
    if (threadIdx.x == 0) g_part[slot][bid] = sh[0];
}

__global__ void finalize_scales_kernel() {
    __shared__ double sh[256];
    int t = threadIdx.x;
    const int cnt[2] = {2048, 1024};
    for (int slot = 0; slot < 2; slot++) {
        double s = 0.0;
        for (int i = t; i < cnt[slot]; i += 256) s += (double)g_part[slot][i];
        sh[t] = s; __syncthreads();
        for (int o = 128; o > 0; o >>= 1) {
            if (t < o) sh[t] += sh[t + o];
            __syncthreads();
        }
        if (t == 0) {
            double n = (slot == 0) ? (double)NQKV * D_MODEL : (double)D_MODEL * D_MODEL;
            g_scales[slot] = fmaxf((float)(sh[0] / n), 1e-5f);
        }
        __syncthreads();
    }
}

__global__ void quantize_kernel(const float4* __restrict__ w, int n4, int slot) {
    int i = blockIdx.x * blockDim.x + threadIdx.x;
    if (i >= n4) return;
    __half* out = (slot == 0) ? g_wq : g_wo;
    float sc = g_scales[slot];
    float4 v = w[i];
    __half h[4];
    h[0] = __float2half_rn(fminf(fmaxf(rintf(v.x / sc), -1.f), 1.f));
    h[1] = __float2half_rn(fminf(fmaxf(rintf(v.y / sc), -1.f), 1.f));
    h[2] = __float2half_rn(fminf(fmaxf(rintf(v.z / sc), -1.f), 1.f));
    h[3] = __float2half_rn(fminf(fmaxf(rintf(v.w / sc), -1.f), 1.f));
    *reinterpret_cast<uint2*>(out + (size_t)4 * i) = *reinterpret_cast<uint2*>(h);
}

__global__ void convert_x_kernel(const float4* __restrict__ x, int n4) {
    int i = blockIdx.x * blockDim.x + threadIdx.x;
    if (i >= n4) return;
    float4 v = x[i];
    __half h[4];
    h[0] = __float2half_rn(v.x); h[1] = __float2half_rn(v.y);
    h[2] = __float2half_rn(v.z); h[3] = __float2half_rn(v.w);
    *reinterpret_cast<uint2*>(g_xh + (size_t)4 * i) = *reinterpret_cast<uint2*>(h);
}

// ---------------- GEMM: C[M,N] = A[M,K]*B[N,K]^T*scale (mma.sync, BK=64, 3-stage) ----------------
// MODE 0: A=g_xh, B=g_wq -> g_qkv [t][b][h][s][d] fp16, RoPE fused (t<2) via smem staging
// MODE 1: A=g_ao, B=g_wo -> outF fp32 row-major
template<int MODE>
__global__ void __launch_bounds__(256, 2) gemm_hmma(float* __restrict__ outF) {
    constexpr int K  = D_MODEL;
    constexpr int KT = K / 64;                 // 32 K-steps
    constexpr int ROWB = 144;                  // 72 halfs padded row (bytes)
    constexpr int STG = 128 * ROWB;            // 18432 bytes/stage/matrix

    extern __shared__ __align__(128) uint8_t smem[];
    const uint32_t sbase = smem_u32(smem);
    const uint32_t offA = 0, offB = 3 * STG;

    const __half* __restrict__ Aop = (MODE == 0) ? g_xh : g_ao;
    const __half* __restrict__ Bop = (MODE == 0) ? g_wq : g_wo;
    const int tid = threadIdx.x, warp = tid >> 5, lane = tid & 31;
    const int wm = warp & 3, wn = warp >> 2;   // 4x2 warp grid, warp tile 32x64
    const int bm = blockIdx.y * 128, bn = blockIdx.x * 128;

    const __half* gA = Aop + (size_t)bm * K;
    const __half* gB = Bop + (size_t)bn * K;

    const int lrow = tid >> 3;                 // base row (adds i*32)
    const int lch  = (tid & 7) * 8;            // half offset within 64-half row

    auto load_stage = [&](int kt) {
        const int slot = kt % 3;
        const __half* ga = gA + kt * 64;
        const __half* gb = gB + kt * 64;
        const uint32_t sa = sbase + offA + slot * STG;
        const uint32_t sb = sbase + offB + slot * STG;
#pragma unroll
        for (int i = 0; i < 4; i++) {
            int row = lrow + i * 32;
            uint32_t so = (uint32_t)(row * ROWB + lch * 2);
            size_t go = (size_t)row * K + lch;
            cp16(sa + so, ga + go);
            cp16(sb + so, gb + go);
        }
    };

    float acc[2][8][4];
#pragma unroll
    for (int i = 0; i < 2; i++)
#pragma unroll
        for (int j = 0; j < 8; j++)
#pragma unroll
            for (int e = 0; e < 4; e++) acc[i][j][e] = 0.f;

    load_stage(0); CP_COMMIT();
    load_stage(1); CP_COMMIT();

    for (int kt = 0; kt < KT; kt++) {
        CP_WAIT1();
        __syncthreads();
        if (kt + 2 < KT) load_stage(kt + 2);
        CP_COMMIT();

        const int slot = kt % 3;
        const uint32_t aB = sbase + offA + slot * STG;
        const uint32_t bB = sbase + offB + slot * STG;
#pragma unroll
        for (int ks = 0; ks < 4; ks++) {
            const uint32_t kcol = (ks * 16 + (lane >> 4) * 8) * 2;
            unsigned aF[2][4], bF[8][2];
#pragma unroll
            for (int mt = 0; mt < 2; mt++)
                ldm_x4(aF[mt], aB + (wm * 32 + mt * 16 + (lane & 15)) * ROWB + kcol);
#pragma unroll
            for (int p = 0; p < 4; p++) {
                unsigned r[4];
                ldm_x4(r, bB + (wn * 64 + p * 16 + (lane & 15)) * ROWB + kcol);
                bF[2 * p][0] = r[0]; bF[2 * p][1] = r[2];
                bF[2 * p + 1][0] = r[1]; bF[2 * p + 1][1] = r[3];
            }
#pragma unroll
            for (int mt = 0; mt < 2; mt++)
#pragma unroll
                for (int nt = 0; nt < 8; nt++)
                    mma16816(acc[mt][nt], aF[mt], bF[nt]);
        }
    }

    const float scale = g_scales[MODE];

    if (MODE == 0) {
        // -------- stage accumulators through smem (reuse pipeline buffers) --------
        constexpr int CST = 132;               // float row stride
        float* sC = reinterpret_cast<float*>(smem);
        __syncthreads();
#pragma unroll
        for (int mt = 0; mt < 2; mt++) {
            int m0 = wm * 32 + mt * 16 + (lane >> 2);
#pragma unroll
            for (int nt = 0; nt < 8; nt++) {
                int n0 = wn * 64 + nt * 8 + (lane & 3) * 2;
                *reinterpret_cast<float2*>(&sC[m0 * CST + n0]) =
                    make_float2(acc[mt][nt][0] * scale, acc[mt][nt][1] * scale);
                *reinterpret_cast<float2*>(&sC[(m0 + 8) * CST + n0]) =
                    make_float2(acc[mt][nt][2] * scale, acc[mt][nt][3] * scale);
            }
        }
        __syncthreads();

        const int t = bn >> 11, h = (bn >> 7) & 15;
        if (t < 2) {
            // RoPE + coalesced store
            const int dgrp = (tid & 15) * 4;
            const float c4 = -0.20762050593046014f;   // -log2(10000)/64
#pragma unroll
            for (int i = 0; i < 8; i++) {
                int row = (tid >> 4) + i * 16;
                int m = bm + row;
                int b = m >> 11, sidx = m & 2047;
                __half* rowp = g_qkv + (((size_t)(t * BATCH + b) * NHEADS + h) * SEQ + sidx) * DHEAD;
                __half lo[4], hi[4];
#pragma unroll
                for (int dd = 0; dd < 4; dd++) {
                    int d = dgrp + dd;
                    float freq = exp2f((float)d * c4);   // 10000^(-d/64)
                    float sn, cs;
                    sincosf((float)sidx * freq, &sn, &cs);
                    float x1 = sC[row * CST + d];
                    float x2 = sC[row * CST + d + 64];
                    lo[dd] = __float2half_rn(x1 * cs - x2 * sn);
                    hi[dd] = __float2half_rn(x1 * sn + x2 * cs);
                }
                *reinterpret_cast<uint2*>(rowp + dgrp)      = *reinterpret_cast<uint2*>(lo);
                *reinterpret_cast<uint2*>(rowp + dgrp + 64) = *reinterpret_cast<uint2*>(hi);
            }
        } else {
            // V: plain coalesced copy
            const int dgrp = (tid & 15) * 8;
#pragma unroll
            for (int i = 0; i < 8; i++) {
                int row = (tid >> 4) + i * 16;
                int m = bm + row;
                int b = m >> 11, sidx = m & 2047;
                __half* rowp = g_qkv + (((size_t)(t * BATCH + b) * NHEADS + h) * SEQ + sidx) * DHEAD;
                __half v[8];
#pragma unroll
                for (int dd = 0; dd < 8; dd++)
                    v[dd] = __float2half_rn(sC[row * CST + dgrp + dd]);
                *reinterpret_cast<uint4*>(rowp + dgrp) = *reinterpret_cast<uint4*>(v);
            }
        }
    } else {
#pragma unroll
        for (int mt = 0; mt < 2; mt++) {
            int m0 = bm + wm * 32 + mt * 16 + (lane >> 2);
#pragma unroll
            for (int nt = 0; nt < 8; nt++) {
                int n0 = bn + wn * 64 + nt * 8 + (lane & 3) * 2;
                float2 v0 = {acc[mt][nt][0] * scale, acc[mt][nt][1] * scale};
                float2 v1 = {acc[mt][nt][2] * scale, acc[mt][nt][3] * scale};
                *reinterpret_cast<float2*>(&outF[(size_t)m0 * D_MODEL + n0]) = v0;
                *reinterpret_cast<float2*>(&outF[(size_t)(m0 + 8) * D_MODEL + n0]) = v1;
            }
        }
    }
}

// ---------------- causal flash attention, Br=Bc=64, 3-stage cp.async ----------------
__global__ void __launch_bounds__(128) flash_kernel() {
    constexpr int ROWB = 272;                 // 136 halfs padded row (bytes)
    constexpr int KSTG = 64 * ROWB;           // 17408 bytes/stage/matrix
    extern __shared__ __align__(128) uint8_t smem[];
    const uint32_t sbase = smem_u32(smem);
    const uint32_t offK = 0, offV = 3 * KSTG;

    const int qt = (gridDim.x - 1) - blockIdx.x;
    const int bh = blockIdx.y;
    const int b = bh >> 4, h = bh & 15;
    const int tid = threadIdx.x, lane = tid & 31, warp = tid >> 5;

    const __half* __restrict__ Qp = g_qkv + ((size_t)(b * NHEADS + h)) * SEQ * DHEAD;
    const __half* __restrict__ Kp = g_qkv + ((size_t)((BATCH + b) * NHEADS + h)) * SEQ * DHEAD;
    const __half* __restrict__ Vp = g_qkv + ((size_t)((2 * BATCH + b) * NHEADS + h)) * SEQ * DHEAD;

    __half* sQ = reinterpret_cast<__half*>(smem);
#pragma unroll
    for (int i = 0; i < 8; i++) {
        int c = tid + i * 128;
        int row = c >> 4, off = (c & 15) * 8;
        *reinterpret_cast<uint4*>(&sQ[row * 136 + off]) =
            *reinterpret_cast<const uint4*>(Qp + (size_t)(qt * 64 + row) * DHEAD + off);
    }
    __syncthreads();
    unsigned qF[8][4];
#pragma unroll
    for (int ks = 0; ks < 8; ks++)
        ldm_x4(qF[ks], sbase + (warp * 16 + (lane & 15)) * ROWB + (ks * 16 + (lane >> 4) * 8) * 2);
    __syncthreads();

    const int lrow = tid >> 4;                // 0..7, +i*8
    const int lch  = (tid & 15) * 8;          // half offset 0..120
    auto load_kv = [&](int j) {
        const int slot = j % 3;
        const uint32_t sk = sbase + offK + slot * KSTG;
        const uint32_t sv = sbase + offV + slot * KSTG;
        const __half* gk = Kp + (size_t)j * 64 * DHEAD;
        const __half* gv = Vp + (size_t)j * 64 * DHEAD;
#pragma unroll
        for (int i = 0; i < 8; i++) {
            int row = lrow + i * 8;
            uint32_t so = (uint32_t)(row * ROWB + lch * 2);
            size_t go = (size_t)row * DHEAD + lch;
            cp16(sk + so, gk + go);
            cp16(sv + so, gv + go);
        }
    };

    load_kv(0); CP_COMMIT();
    if (1 <= qt) load_kv(1);
    CP_COMMIT();

    float oacc[16][4];
#pragma unroll
    for (int i = 0; i < 16; i++)
#pragma unroll
        for (int e = 0; e < 4; e++) oacc[i][e] = 0.f;
    float mx0 = -1e30f, mx1 = -1e30f, l0 = 0.f, l1 = 0.f;
    const float sscale = 0.08838834764831845f;
    const int qrow0 = qt * 64 + warp * 16 + (lane >> 2);

    for (int j = 0; j <= qt; j++) {
        CP_WAIT1();
        __syncthreads();
        if (j + 2 <= qt) load_kv(j + 2);
        CP_COMMIT();

        const int slot = j % 3;
        const uint32_t kB = sbase + offK + slot * KSTG;
        const uint32_t vB = sbase + offV + slot * KSTG;

        float sacc[8][4];
#pragma unroll
        for (int nt = 0; nt < 8; nt++)
#pragma unroll
            for (int e = 0; e < 4; e++) sacc[nt][e] = 0.f;
#pragma unroll
        for (int ks = 0; ks < 8; ks++) {
            const uint32_t kcol = (ks * 16 + (lane >> 4) * 8) * 2;
            unsigned bF[8][2];
#pragma unroll
            for (int p = 0; p < 4; p++) {
                unsigned r[4];
                ldm_x4(r, kB + (p * 16 + (lane & 15)) * ROWB + kcol);
                bF[2 * p][0] = r[0]; bF[2 * p][1] = r[2];
                bF[2 * p + 1][0] = r[1]; bF[2 * p + 1][1] = r[3];
            }
#pragma unroll
            for (int nt = 0; nt < 8; nt++) mma16816(sacc[nt], qF[ks], bF[nt]);
        }

#pragma unroll
        for (int nt = 0; nt < 8; nt++) {
            int col = j * 64 + nt * 8 + (lane & 3) * 2;
#pragma unroll
            for (int e = 0; e < 4; e++) {
                int cc = col + (e & 1);
                int qr = qrow0 + (e >> 1) * 8;
                float v = sacc[nt][e] * sscale;
                if (j == qt && cc > qr) v = -1e30f;
                sacc[nt][e] = v;
            }
        }

        float rm0 = -1e30f, rm1 = -1e30f;
#pragma unroll
        for (int nt = 0; nt < 8; nt++) {
            rm0 = fmaxf(rm0, fmaxf(sacc[nt][0], sacc[nt][1]));
            rm1 = fmaxf(rm1, fmaxf(sacc[nt][2], sacc[nt][3]));
        }
        rm0 = fmaxf(rm0, __shfl_xor_sync(0xffffffffu, rm0, 1));
        rm0 = fmaxf(rm0, __shfl_xor_sync(0xffffffffu, rm0, 2));
        rm1 = fmaxf(rm1, __shfl_xor_sync(0xffffffffu, rm1, 1));
        rm1 = fmaxf(rm1, __shfl_xor_sync(0xffffffffu, rm1, 2));
        float mn0 = fmaxf(mx0, rm0), mn1 = fmaxf(mx1, rm1);
        float al0 = __expf(mx0 - mn0), al1 = __expf(mx1 - mn1);
        mx0 = mn0; mx1 = mn1;

        float rs0 = 0.f, rs1 = 0.f;
#pragma unroll
        for (int nt = 0; nt < 8; nt++) {
            float p0 = __expf(sacc[nt][0] - mn0), p1 = __expf(sacc[nt][1] - mn0);
            float p2 = __expf(sacc[nt][2] - mn1), p3 = __expf(sacc[nt][3] - mn1);
            sacc[nt][0] = p0; sacc[nt][1] = p1; sacc[nt][2] = p2; sacc[nt][3] = p3;
            rs0 += p0 + p1; rs1 += p2 + p3;
        }
        rs0 += __shfl_xor_sync(0xffffffffu, rs0, 1);
        rs0 += __shfl_xor_sync(0xffffffffu, rs0, 2);
        rs1 += __shfl_xor_sync(0xffffffffu, rs1, 1);
        rs1 += __shfl_xor_sync(0xffffffffu, rs1, 2);
        l0 = l0 * al0 + rs0; l1 = l1 * al1 + rs1;
#pragma unroll
        for (int i = 0; i < 16; i++) {
            oacc[i][0] *= al0; oacc[i][1] *= al0;
            oacc[i][2] *= al1; oacc[i][3] *= al1;
        }

        unsigned aP[4][4];
#pragma unroll
        for (int kk = 0; kk < 4; kk++) {
            aP[kk][0] = pack2(sacc[2 * kk][0], sacc[2 * kk][1]);
            aP[kk][1] = pack2(sacc[2 * kk][2], sacc[2 * kk][3]);
            aP[kk][2] = pack2(sacc[2 * kk + 1][0], sacc[2 * kk + 1][1]);
            aP[kk][3] = pack2(sacc[2 * kk + 1][2], sacc[2 * kk + 1][3]);
        }

#pragma unroll
        for (int kk = 0; kk < 4; kk++) {
            int kvrow = kk * 16 + ((lane >> 3) & 1) * 8 + (lane & 7);
#pragma unroll
            for (int p = 0; p < 8; p++) {
                unsigned r[4];
                int dcol = p * 16 + (lane >> 4) * 8;
                ldm_x4_t(r, vB + kvrow * ROWB + dcol * 2);
                unsigned b0[2] = {r[0], r[1]}, b1[2] = {r[2], r[3]};
                mma16816(oacc[2 * p], aP[kk], b0);
                mma16816(oacc[2 * p + 1], aP[kk], b1);
            }
        }
    }

    float il0 = 1.f / l0, il1 = 1.f / l1;
    int s0 = qt * 64 + warp * 16 + (lane >> 2);
    size_t rb0 = ((size_t)(b * SEQ + s0)) * D_MODEL + h * DHEAD;
    size_t rb1 = rb0 + (size_t)8 * D_MODEL;
#pragma unroll
    for (int p = 0; p < 16; p++) {
        int d = p * 8 + (lane & 3) * 2;
        *reinterpret_cast<__half2*>(&g_ao[rb0 + d]) = __floats2half2_rn(oacc[p][0] * il0, oacc[p][1] * il0);
        *reinterpret_cast<__half2*>(&g_ao[rb1 + d]) = __floats2half2_rn(oacc[p][2] * il1, oacc[p][3] * il1);
    }
}

// ---------------- launcher ----------------
extern "C" void kernel_launch(void* const* d_in, const int* in_sizes, int n_in,
                              void* d_out, int out_size) {
    const float* x    = (const float*)d_in[0];
    const float* wqkv = (const float*)d_in[1];
    const float* wout = (const float*)d_in[2];
    // d_in[3] = causal mask (static; unused)

    constexpr int GEMM_SMEM  = 6 * 128 * 144;      // 110592
    constexpr int FLASH_SMEM = 6 * 64 * 272;       // 104448
    cudaFuncSetAttribute(gemm_hmma<0>, cudaFuncAttributeMaxDynamicSharedMemorySize, GEMM_SMEM);
    cudaFuncSetAttribute(gemm_hmma<1>, cudaFuncAttributeMaxDynamicSharedMemorySize, GEMM_SMEM);
    cudaFuncSetAttribute(flash_kernel, cudaFuncAttributeMaxDynamicSharedMemorySize, FLASH_SMEM);

    // 5 prep launches -> gemm_hmma<0> is launch index 5 (ncu -s 5 -c 1 captures it)
    reduce_abs_all<<<3072, 256>>>(wqkv, wout);
    finalize_scales_kernel<<<1, 256>>>();
    quantize_kernel<<<(NQKV * D_MODEL / 4) / 256, 256>>>((const float4*)wqkv, NQKV * D_MODEL / 4, 0);
    quantize_kernel<<<(D_MODEL * D_MODEL / 4) / 256, 256>>>((const float4*)wout, D_MODEL * D_MODEL / 4, 1);
    convert_x_kernel<<<(MROWS * D_MODEL / 4) / 256, 256>>>((const float4*)x, MROWS * D_MODEL / 4);

    gemm_hmma<0><<<dim3(NQKV / 128, MROWS / 128), 256, GEMM_SMEM>>>(nullptr);
    flash_kernel<<<dim3(SEQ / 64, BATCH * NHEADS), 128, FLASH_SMEM>>>();
    gemm_hmma<1><<<dim3(D_MODEL / 128, MROWS / 128), 256, GEMM_SMEM>>>((float*)d_out);
}